// round 15
// baseline (speedup 1.0000x reference)
#include <cuda_runtime.h>
#include <cstdint>

// Problem dims (fixed by the reference setup)
#define BATCH   8
#define NT      1024          // N*T
#define MLANES  64            // M
#define LPTS    16            // L
#define NEMBD   128
#define EDIM    12
#define NPOS    (BATCH * NT * MLANES)   // 524288

#define ROWS_PB 4             // agent rows per block
#define POS_PB  (ROWS_PB * MLANES)      // 256 positions per block (1 per thread)
#define TPB     256

typedef unsigned long long u64;

// ---------------------------------------------------------------------------
// packed f32x2 helpers (Blackwell)
// ---------------------------------------------------------------------------
__device__ __forceinline__ u64 pack2(float a, float b) {
    u64 r;
    asm("mov.b64 %0, {%1,%2};" : "=l"(r) : "f"(a), "f"(b));
    return r;
}
__device__ __forceinline__ void unpack2(u64 v, float& a, float& b) {
    asm("mov.b64 {%0,%1}, %2;" : "=f"(a), "=f"(b) : "l"(v));
}
__device__ __forceinline__ void fma2(u64& acc, u64 a, u64 b) {
    asm("fma.rn.f32x2 %0, %1, %2, %0;" : "+l"(acc) : "l"(a), "l"(b));
}

__device__ __forceinline__ float4 dx_at(float px, float py, float ps, float pc,
                                        float flag1, float4 q) {
    float f2 = (q.x == 0.f && q.y == 0.f && q.z == 0.f && q.w == 0.f) ? 0.f : 1.f;
    float f  = flag1 * f2;
    float dxw = px - q.x;
    float dyw = py - q.y;
    float dX = (dxw * q.w + dyw * q.z) * 0.1f * f;   // delta_x / 10
    float dY = (-dxw * q.z + dyw * q.w) * 0.1f * f;  // delta_y / 10
    float ds = (ps * q.w - pc * q.z) * f;
    float dc = (pc * q.w + ps * q.z) * f;
    return make_float4(dX, dY, ds, dc);
}

// ---------------------------------------------------------------------------
// Fused kernel, SHUFFLE-BROADCAST build (no edge smem round-trip):
//  Phase A: each thread computes its own position's edge row -> 6 packed u64
//           held in REGISTERS. No STS, no Phase-B LDS, no inter-phase barrier.
//  Phase B: warp iterates its 32 lane-owned positions; edge pairs broadcast
//           via __shfl_sync (shuffle path, not L1tex); lane owns 4 channels;
//           one coalesced STG.128 per position.
// L1tex wavefronts per position drop from ~13 to ~6.5 (slane LDS + STG only).
// ---------------------------------------------------------------------------
__global__ void __launch_bounds__(TPB, 3)
fused_kernel(const float* __restrict__ agent,
             const float* __restrict__ lane,
             const float* __restrict__ W,
             const float* __restrict__ bias,
             float* __restrict__ out) {
    __shared__ __align__(16) float4 slane[LPTS * MLANES];    // [l][m], 16 KB
    __shared__ float sagent[ROWS_PB * 8];                    // 128 B

    const int tid  = threadIdx.x;
    const int warp = tid >> 5;
    const int lid  = tid & 31;
    const size_t row0 = (size_t)blockIdx.x * ROWS_PB;        // global agent row base
    const int b = (int)(row0 >> 10);

    // ---- Phase 0: stage lane (transposed [l][m]) + agent rows ----
    const float4* lg = reinterpret_cast<const float4*>(lane) + (size_t)b * MLANES * LPTS;
#pragma unroll
    for (int k = 0; k < 4; k++) {
        int s = tid + k * TPB;            // s = l*64 + m
        int l = s >> 6, m = s & 63;
        slane[s] = __ldg(lg + m * LPTS + l);
    }
    if (tid < ROWS_PB * 8)
        sagent[tid] = __ldg(agent + row0 * 8 + tid);
    __syncthreads();

    // ---- Phase A: this thread's position = tid ----
    u64 ev_own[6];
    {
        const int p = tid;                // local position
        const int r = p >> 6, m = p & 63;
        const float* ar = sagent + r * 8;
        float a0 = ar[0], a1 = ar[1], a2 = ar[2], a3 = ar[3];
        float a4 = ar[4], a5 = ar[5], a6 = ar[6], a7 = ar[7];
        float flag1 = (a0 == 0.f && a1 == 0.f && a2 == 0.f && a3 == 0.f &&
                       a4 == 0.f && a5 == 0.f && a6 == 0.f && a7 == 0.f) ? 0.f : 1.f;
        float px = a0, py = a1, ps = a3, pc = a4;

        float bestAbs = 3.4e38f;
        int   bestl   = 0;
#pragma unroll
        for (int l = 0; l < LPTS; l++) {
            float4 q = slane[l * MLANES + m];     // contiguous LDS.128, conflict-free
            float f2 = (q.x == 0.f && q.y == 0.f && q.z == 0.f && q.w == 0.f) ? 0.f : 1.f;
            float f01 = 0.1f * flag1 * f2;
            float dxw = px - q.x;
            float dyw = py - q.y;
            float aX = fabsf((dxw * q.w + dyw * q.z) * f01);
            if (aX < bestAbs) { bestAbs = aX; bestl = l; }   // strict < = first-min
        }

        float4 mp  = dx_at(px, py, ps, pc, flag1, slane[bestl * MLANES + m]);
        float4 el0 = dx_at(px, py, ps, pc, flag1, slane[0 * MLANES + m]);
        float4 elL = dx_at(px, py, ps, pc, flag1, slane[(LPTS - 1) * MLANES + m]);

        ev_own[0] = pack2(mp.x,  mp.y);
        ev_own[1] = pack2(mp.z,  mp.w);
        ev_own[2] = pack2(el0.x, el0.y);
        ev_own[3] = pack2(el0.z, el0.w);
        ev_own[4] = pack2(elL.x, elL.y);
        ev_own[5] = pack2(elL.z, elL.w);
    }

    // ---- Weights for 4 channels/lane (no barrier needed: Phase B is warp-local) ----
    const int e0 = lid * 4;               // this lane's first channel
    u64 wp[4][6];
#pragma unroll
    for (int c = 0; c < 4; c++) {
        const float* wrow = W + (e0 + c) * EDIM;
#pragma unroll
        for (int k = 0; k < 6; k++)
            wp[c][k] = pack2(__ldg(wrow + 2 * k), __ldg(wrow + 2 * k + 1));
    }
    const float4 b4 = *reinterpret_cast<const float4*>(bias + e0);  // 16B-aligned

    // ---- Phase B: broadcast each lane's edge row via shuffles; 1 STG.128/pos ----
    float* obase = out + ((size_t)blockIdx.x * POS_PB + (size_t)warp * 32) * NEMBD + e0;

#pragma unroll 2
    for (int src = 0; src < 32; src++) {
        u64 ev0 = __shfl_sync(0xffffffffu, ev_own[0], src);
        u64 ev1 = __shfl_sync(0xffffffffu, ev_own[1], src);
        u64 ev2 = __shfl_sync(0xffffffffu, ev_own[2], src);
        u64 ev3 = __shfl_sync(0xffffffffu, ev_own[3], src);
        u64 ev4 = __shfl_sync(0xffffffffu, ev_own[4], src);
        u64 ev5 = __shfl_sync(0xffffffffu, ev_own[5], src);

        u64 a0 = 0ull, a1 = 0ull, a2 = 0ull, a3 = 0ull;
        fma2(a0, ev0, wp[0][0]); fma2(a1, ev0, wp[1][0]); fma2(a2, ev0, wp[2][0]); fma2(a3, ev0, wp[3][0]);
        fma2(a0, ev1, wp[0][1]); fma2(a1, ev1, wp[1][1]); fma2(a2, ev1, wp[2][1]); fma2(a3, ev1, wp[3][1]);
        fma2(a0, ev2, wp[0][2]); fma2(a1, ev2, wp[1][2]); fma2(a2, ev2, wp[2][2]); fma2(a3, ev2, wp[3][2]);
        fma2(a0, ev3, wp[0][3]); fma2(a1, ev3, wp[1][3]); fma2(a2, ev3, wp[2][3]); fma2(a3, ev3, wp[3][3]);
        fma2(a0, ev4, wp[0][4]); fma2(a1, ev4, wp[1][4]); fma2(a2, ev4, wp[2][4]); fma2(a3, ev4, wp[3][4]);
        fma2(a0, ev5, wp[0][5]); fma2(a1, ev5, wp[1][5]); fma2(a2, ev5, wp[2][5]); fma2(a3, ev5, wp[3][5]);

        float lo, hi;
        float4 o;
        unpack2(a0, lo, hi); o.x = lo + hi + b4.x;
        unpack2(a1, lo, hi); o.y = lo + hi + b4.y;
        unpack2(a2, lo, hi); o.z = lo + hi + b4.z;
        unpack2(a3, lo, hi); o.w = lo + hi + b4.w;

        __stcs(reinterpret_cast<float4*>(obase + (size_t)src * NEMBD), o);
    }
}

// ---------------------------------------------------------------------------
// Launch: inputs in metadata order: agent, lane, W, b. Output fp32.
// ---------------------------------------------------------------------------
extern "C" void kernel_launch(void* const* d_in, const int* in_sizes, int n_in,
                              void* d_out, int out_size) {
    const float* agent = (const float*)d_in[0];
    const float* lane  = (const float*)d_in[1];
    const float* W     = (const float*)d_in[2];
    const float* bias  = (const float*)d_in[3];
    float* out = (float*)d_out;

    // 524288 positions / 256 per block = 2048 blocks
    fused_kernel<<<NPOS / POS_PB, TPB>>>(agent, lane, W, bias, out);
}

// round 16
// speedup vs baseline: 1.8983x; 1.8983x over previous
#include <cuda_runtime.h>
#include <cstdint>

// Problem dims (fixed by the reference setup)
#define BATCH   8
#define NT      1024          // N*T
#define MLANES  64            // M
#define LPTS    16            // L
#define NEMBD   128
#define EDIM    12
#define NPOS    (BATCH * NT * MLANES)   // 524288

#define ROWS_PB 8             // agent rows per block
#define POS_PB  (ROWS_PB * MLANES)      // 512 positions per block
#define TPB     256
#define CHUNK   (POS_PB / 4)  // 128 positions per warp-pair

typedef unsigned long long u64;

// ---------------------------------------------------------------------------
// packed f32x2 helpers (Blackwell)
// ---------------------------------------------------------------------------
__device__ __forceinline__ u64 pack2(float a, float b) {
    u64 r;
    asm("mov.b64 %0, {%1,%2};" : "=l"(r) : "f"(a), "f"(b));
    return r;
}
__device__ __forceinline__ void unpack2(u64 v, float& a, float& b) {
    asm("mov.b64 {%0,%1}, %2;" : "=f"(a), "=f"(b) : "l"(v));
}
__device__ __forceinline__ void fma2(u64& acc, u64 a, u64 b) {
    asm("fma.rn.f32x2 %0, %1, %2, %0;" : "+l"(acc) : "l"(a), "l"(b));
}

__device__ __forceinline__ float4 dx_at(float px, float py, float ps, float pc,
                                        float flag1, float4 q) {
    float f2 = (q.x == 0.f && q.y == 0.f && q.z == 0.f && q.w == 0.f) ? 0.f : 1.f;
    float f  = flag1 * f2;
    float dxw = px - q.x;
    float dyw = py - q.y;
    float dX = (dxw * q.w + dyw * q.z) * 0.1f * f;   // delta_x / 10
    float dY = (-dxw * q.z + dyw * q.w) * 0.1f * f;  // delta_y / 10
    float ds = (ps * q.w - pc * q.z) * f;
    float dc = (pc * q.w + ps * q.z) * f;
    return make_float4(dX, dY, ds, dc);
}

// ---------------------------------------------------------------------------
// Fused kernel: edge features (smem-local) + projection.
// ILP-4 / low-CTA build: launch_bounds(256,2) -> 128-reg budget, 2 CTAs/SM
// (lower L1tex-queue contention), warp-pair Phase B with 4-position unroll:
// 12 up-front LDS.128 (MLP=12), 4 independent FMA chains, 8 stores/iter.
// ---------------------------------------------------------------------------
__global__ void __launch_bounds__(TPB, 2)
fused_kernel(const float* __restrict__ agent,
             const float* __restrict__ lane,
             const float* __restrict__ W,
             const float* __restrict__ bias,
             float* __restrict__ out) {
    __shared__ __align__(16) float4 slane[LPTS * MLANES];    // [l][m], 16 KB
    __shared__ float sagent[ROWS_PB * 8];                    // 256 B
    __shared__ __align__(16) float sedge[POS_PB * EDIM];     // 24 KB

    const int tid  = threadIdx.x;
    const size_t row0 = (size_t)blockIdx.x * ROWS_PB;        // global agent row base
    const int b = (int)(row0 >> 10);

    // ---- Phase 0: stage lane (transposed [l][m]) + agent rows ----
    const float4* lg = reinterpret_cast<const float4*>(lane) + (size_t)b * MLANES * LPTS;
#pragma unroll
    for (int k = 0; k < 4; k++) {
        int s = tid + k * 256;            // s = l*64 + m
        int l = s >> 6, m = s & 63;
        slane[s] = __ldg(lg + m * LPTS + l);
    }
    if (tid < ROWS_PB * 8)
        sagent[tid] = __ldg(agent + row0 * 8 + tid);
    __syncthreads();

    // ---- Phase A: edge features into smem (2 positions per thread) ----
#pragma unroll
    for (int it = 0; it < 2; it++) {
        int p = tid + it * 256;           // local position
        int r = p >> 6, m = p & 63;
        const float* ar = sagent + r * 8;
        float a0 = ar[0], a1 = ar[1], a2 = ar[2], a3 = ar[3];
        float a4 = ar[4], a5 = ar[5], a6 = ar[6], a7 = ar[7];
        float flag1 = (a0 == 0.f && a1 == 0.f && a2 == 0.f && a3 == 0.f &&
                       a4 == 0.f && a5 == 0.f && a6 == 0.f && a7 == 0.f) ? 0.f : 1.f;
        float px = a0, py = a1, ps = a3, pc = a4;

        float bestAbs = 3.4e38f;
        int   bestl   = 0;
#pragma unroll
        for (int l = 0; l < LPTS; l++) {
            float4 q = slane[l * MLANES + m];     // contiguous LDS.128, conflict-free
            float f2 = (q.x == 0.f && q.y == 0.f && q.z == 0.f && q.w == 0.f) ? 0.f : 1.f;
            float f01 = 0.1f * flag1 * f2;
            float dxw = px - q.x;
            float dyw = py - q.y;
            float aX = fabsf((dxw * q.w + dyw * q.z) * f01);
            if (aX < bestAbs) { bestAbs = aX; bestl = l; }   // strict < = first-min
        }

        float4 mp  = dx_at(px, py, ps, pc, flag1, slane[bestl * MLANES + m]);
        float4 el0 = dx_at(px, py, ps, pc, flag1, slane[0 * MLANES + m]);
        float4 elL = dx_at(px, py, ps, pc, flag1, slane[(LPTS - 1) * MLANES + m]);

        float4* ep = reinterpret_cast<float4*>(sedge + p * EDIM);   // rows 16B-aligned
        ep[0] = mp;
        ep[1] = el0;
        ep[2] = elL;
    }

    // ---- Per-lane weights for 2 channels (loaded after Phase A) ----
    const int warp = tid >> 5;
    const int lid  = tid & 31;
    const int e0   = (warp & 1) * 64 + lid * 2;   // this lane's first channel

    u64 wp0[6], wp1[6];
#pragma unroll
    for (int k = 0; k < 6; k++) {
        wp0[k] = pack2(__ldg(W + (e0 + 0) * EDIM + 2 * k), __ldg(W + (e0 + 0) * EDIM + 2 * k + 1));
        wp1[k] = pack2(__ldg(W + (e0 + 1) * EDIM + 2 * k), __ldg(W + (e0 + 1) * EDIM + 2 * k + 1));
    }
    const u64 b0 = pack2(__ldg(bias + e0 + 0), 0.f);
    const u64 b1 = pack2(__ldg(bias + e0 + 1), 0.f);

    __syncthreads();

    // ---- Phase B: warp-pair owns a contiguous 128-position chunk.
    //      4-position manual unroll: 12 up-front LDS.128 (MLP=12),
    //      4 independent accumulator chains, pointer bumps, __stcs stores.
    const int pair = warp >> 1;
    const ulonglong2* eptr =
        reinterpret_cast<const ulonglong2*>(sedge + pair * CHUNK * EDIM);
    float* optr = out + ((size_t)blockIdx.x * POS_PB + (size_t)pair * CHUNK) * NEMBD + e0;

#pragma unroll 1
    for (int it = 0; it < CHUNK / 4; it++) {
        // Load 4 positions' edge rows up front (12 independent LDS.128)
        ulonglong2 qa0 = eptr[0],  qa1 = eptr[1],  qa2 = eptr[2];    // position A
        ulonglong2 qb0 = eptr[3],  qb1 = eptr[4],  qb2 = eptr[5];    // position B
        ulonglong2 qc0 = eptr[6],  qc1 = eptr[7],  qc2 = eptr[8];    // position C
        ulonglong2 qd0 = eptr[9],  qd1 = eptr[10], qd2 = eptr[11];   // position D
        eptr += 12;

        u64 evA[6] = { qa0.x, qa0.y, qa1.x, qa1.y, qa2.x, qa2.y };
        u64 evB[6] = { qb0.x, qb0.y, qb1.x, qb1.y, qb2.x, qb2.y };
        u64 evC[6] = { qc0.x, qc0.y, qc1.x, qc1.y, qc2.x, qc2.y };
        u64 evD[6] = { qd0.x, qd0.y, qd1.x, qd1.y, qd2.x, qd2.y };

        u64 aA0 = b0, aA1 = b1, aB0 = b0, aB1 = b1;
        u64 aC0 = b0, aC1 = b1, aD0 = b0, aD1 = b1;
#pragma unroll
        for (int k = 0; k < 6; k++) {
            fma2(aA0, evA[k], wp0[k]); fma2(aA1, evA[k], wp1[k]);
            fma2(aB0, evB[k], wp0[k]); fma2(aB1, evB[k], wp1[k]);
            fma2(aC0, evC[k], wp0[k]); fma2(aC1, evC[k], wp1[k]);
            fma2(aD0, evD[k], wp0[k]); fma2(aD1, evD[k], wp1[k]);
        }

        float x0, y0, x1, y1;
        unpack2(aA0, x0, y0); unpack2(aA1, x1, y1);
        __stcs(reinterpret_cast<float2*>(optr + 0 * NEMBD),
               make_float2(x0 + y0, x1 + y1));
        unpack2(aB0, x0, y0); unpack2(aB1, x1, y1);
        __stcs(reinterpret_cast<float2*>(optr + 1 * NEMBD),
               make_float2(x0 + y0, x1 + y1));
        unpack2(aC0, x0, y0); unpack2(aC1, x1, y1);
        __stcs(reinterpret_cast<float2*>(optr + 2 * NEMBD),
               make_float2(x0 + y0, x1 + y1));
        unpack2(aD0, x0, y0); unpack2(aD1, x1, y1);
        __stcs(reinterpret_cast<float2*>(optr + 3 * NEMBD),
               make_float2(x0 + y0, x1 + y1));
        optr += 4 * NEMBD;
    }
}

// ---------------------------------------------------------------------------
// Launch: inputs in metadata order: agent, lane, W, b. Output fp32.
// ---------------------------------------------------------------------------
extern "C" void kernel_launch(void* const* d_in, const int* in_sizes, int n_in,
                              void* d_out, int out_size) {
    const float* agent = (const float*)d_in[0];
    const float* lane  = (const float*)d_in[1];
    const float* W     = (const float*)d_in[2];
    const float* bias  = (const float*)d_in[3];
    float* out = (float*)d_out;

    fused_kernel<<<NPOS / POS_PB, TPB>>>(agent, lane, W, bias, out);
}